// round 1
// baseline (speedup 1.0000x reference)
#include <cuda_runtime.h>
#include <math.h>

#define B   16
#define TK  2048
#define STK 64
#define N   512

// output layout (flattened tuple, row-major each)
#define OFF_CT    0
#define OFF_ATTN  (B*N)
#define OFF_COV   (OFF_ATTN + B*TK)
#define OFF_SCT   (OFF_COV + B*TK)
#define OFF_SATTN (OFF_SCT + B*N)

// scratch
__device__ float g_dec[B*N];
__device__ float g_sdec[B*N];
__device__ float g_scores[B*TK];
__device__ float g_sscores[B*STK];

// ---------------------------------------------------------------------------
// dec[b][n] = bias[n] + dot(s[b,:], W[n,:])   — warp per output element
// which: 0 -> g_dec, 1 -> g_sdec
// ---------------------------------------------------------------------------
__global__ void dec_kernel(const float* __restrict__ s, const float* __restrict__ W,
                           const float* __restrict__ bias, int which)
{
    int gw   = (blockIdx.x * blockDim.x + threadIdx.x) >> 5;
    int lane = threadIdx.x & 31;
    if (gw >= B * N) return;
    int b = gw >> 9;          // / N
    int n = gw & (N - 1);
    const float4* sv = (const float4*)(s + (size_t)b * N);
    const float4* wv = (const float4*)(W + (size_t)n * N);
    float acc = 0.f;
#pragma unroll
    for (int i = 0; i < 4; i++) {
        float4 a = sv[i * 32 + lane];
        float4 w = wv[i * 32 + lane];
        acc = fmaf(a.x, w.x, fmaf(a.y, w.y, fmaf(a.z, w.z, fmaf(a.w, w.w, acc))));
    }
#pragma unroll
    for (int o = 16; o; o >>= 1) acc += __shfl_xor_sync(0xffffffffu, acc, o);
    if (lane == 0) {
        float* dst = which ? g_sdec : g_dec;
        dst[gw] = acc + bias[n];
    }
}

// ---------------------------------------------------------------------------
// scores[b*T+t] = dot(v, tanh(feat[b*T+t,:] + dec[b,:] + cov[b,t]*wc))
// warp per token. Streams the big encoder_feature tensor.
// which: 0 -> word (g_dec/g_scores), 1 -> sentence (g_sdec/g_sscores)
// ---------------------------------------------------------------------------
__global__ void score_kernel(const float* __restrict__ feat,
                             const float* __restrict__ v,
                             const float* __restrict__ wc,
                             const float* __restrict__ cov,
                             int T, int which)
{
    int gw   = (blockIdx.x * blockDim.x + threadIdx.x) >> 5;
    int lane = threadIdx.x & 31;
    if (gw >= B * T) return;
    int b = gw / T;
    const float* dec = which ? g_sdec : g_dec;
    float c = cov ? cov[gw] : 0.f;
    const float4* fv = (const float4*)(feat + (size_t)gw * N);
    const float4* dv = (const float4*)(dec + (size_t)b * N);
    const float4* vv = (const float4*)v;
    const float4* wv = (const float4*)wc;
    float acc = 0.f;
#pragma unroll
    for (int i = 0; i < 4; i++) {
        int j = i * 32 + lane;
        float4 f  = fv[j];
        float4 d  = dv[j];
        float4 vw = vv[j];
        float ex, ey, ez, ew;
        if (wc) {
            float4 w = wv[j];
            ex = tanhf(f.x + d.x + c * w.x);
            ey = tanhf(f.y + d.y + c * w.y);
            ez = tanhf(f.z + d.z + c * w.z);
            ew = tanhf(f.w + d.w + c * w.w);
        } else {
            ex = tanhf(f.x + d.x);
            ey = tanhf(f.y + d.y);
            ez = tanhf(f.z + d.z);
            ew = tanhf(f.w + d.w);
        }
        acc = fmaf(ex, vw.x, fmaf(ey, vw.y, fmaf(ez, vw.z, fmaf(ew, vw.w, acc))));
    }
#pragma unroll
    for (int o = 16; o; o >>= 1) acc += __shfl_xor_sync(0xffffffffu, acc, o);
    if (lane == 0) {
        float* dst = which ? g_sscores : g_scores;
        dst[gw] = acc;
    }
}

// ---------------------------------------------------------------------------
// Sentence-level: softmax over 64, mask-renorm, write sent_attn_dist,
// then sent_c_t[b,n] = sum_t a[t]*sent_enc_outputs[b,t,n].  One block per b.
// ---------------------------------------------------------------------------
__global__ void sent_kernel(const float* __restrict__ smask,
                            const float* __restrict__ sout,
                            float* __restrict__ o_sattn,
                            float* __restrict__ o_sct)
{
    __shared__ float sa[STK];
    int b = blockIdx.x, tid = threadIdx.x; // 256 threads
    if (tid < STK) sa[tid] = g_sscores[b * STK + tid];
    __syncthreads();
    if (tid == 0) {
        float m = -1e30f;
#pragma unroll
        for (int t = 0; t < STK; t++) m = fmaxf(m, sa[t]);
        float s = 0.f;
#pragma unroll
        for (int t = 0; t < STK; t++) { float e = expf(sa[t] - m); sa[t] = e; s += e; }
        float inv = 1.f / s;
        float s2 = 0.f;
#pragma unroll
        for (int t = 0; t < STK; t++) { float a = sa[t] * inv * smask[b * STK + t]; sa[t] = a; s2 += a; }
        float inv2 = 1.f / s2;
#pragma unroll
        for (int t = 0; t < STK; t++) sa[t] *= inv2;
    }
    __syncthreads();
    if (tid < STK) o_sattn[b * STK + tid] = sa[tid];
    for (int n = tid; n < N; n += blockDim.x) {
        float acc = 0.f;
#pragma unroll 8
        for (int t = 0; t < STK; t++)
            acc = fmaf(sa[t], sout[((size_t)(b * STK + t)) * N + n], acc);
        o_sct[b * N + n] = acc;
    }
}

// ---------------------------------------------------------------------------
// block reduction helpers (512 threads = 16 warps)
// ---------------------------------------------------------------------------
__device__ __forceinline__ float blk_reduce(float v, float* red, int tid, int is_max)
{
#pragma unroll
    for (int o = 16; o; o >>= 1) {
        float u = __shfl_xor_sync(0xffffffffu, v, o);
        v = is_max ? fmaxf(v, u) : (v + u);
    }
    if ((tid & 31) == 0) red[tid >> 5] = v;
    __syncthreads();
    if (tid < 32) {
        v = (tid < 16) ? red[tid] : (is_max ? -1e30f : 0.f);
#pragma unroll
        for (int o = 8; o; o >>= 1) {
            float u = __shfl_xor_sync(0xffffffffu, v, o);
            v = is_max ? fmaxf(v, u) : (v + u);
        }
        if (tid == 0) red[0] = v;
    }
    __syncthreads();
    v = red[0];
    __syncthreads();
    return v;
}

__device__ __forceinline__ int seg_of(int t, const int* pos)
{
    // count of pos[i] <= t  (upper_bound)
    int lo = 0, hi = STK;
    while (lo < hi) {
        int mid = (lo + hi) >> 1;
        if (pos[mid] <= t) lo = mid + 1; else hi = mid;
    }
    return lo;
}

// ---------------------------------------------------------------------------
// Word-level softmax + mask renorm + ragged per-sentence renorm + coverage.
// One block per b (512 threads).  Also zeroes the c_t output region.
// ---------------------------------------------------------------------------
__global__ void word_softmax_kernel(const float* __restrict__ mask,
                                    const float* __restrict__ cov,
                                    const int* __restrict__ spos,
                                    const float* __restrict__ sattn_in,
                                    float* __restrict__ o_attn,
                                    float* __restrict__ o_cov,
                                    float* __restrict__ o_ct)
{
    __shared__ float sa[TK];
    __shared__ int   pos[STK];
    __shared__ float segsum[STK];
    __shared__ float sattn[STK];
    __shared__ float red[16];
    int b = blockIdx.x, tid = threadIdx.x; // 512 threads

    if (tid < STK) {
        pos[tid]    = spos[b * STK + tid];
        segsum[tid] = 0.f;
        sattn[tid]  = sattn_in[b * STK + tid];
    }
    o_ct[b * N + tid] = 0.f;   // zero c_t region for later atomics (N == blockDim)

    float m = -1e30f;
    for (int t = tid; t < TK; t += 512) {
        float s = g_scores[b * TK + t];
        sa[t] = s;
        m = fmaxf(m, s);
    }
    m = blk_reduce(m, red, tid, 1);

    float ls = 0.f;
    for (int t = tid; t < TK; t += 512) {
        float e = expf(sa[t] - m);
        sa[t] = e;
        ls += e;
    }
    float S = blk_reduce(ls, red, tid, 0);
    float invS = 1.f / S;

    float ls2 = 0.f;
    for (int t = tid; t < TK; t += 512) {
        float a = sa[t] * invS * mask[b * TK + t];
        sa[t] = a;
        ls2 += a;
    }
    float S2 = blk_reduce(ls2, red, tid, 0);
    float invS2 = 1.f / S2;

    for (int t = tid; t < TK; t += 512) {
        float a = sa[t] * invS2;
        sa[t] = a;
        o_attn[b * TK + t] = a;
        int sg = seg_of(t, pos);
        if (sg < STK) atomicAdd(&segsum[sg], a);
    }
    __syncthreads();

    for (int t = tid; t < TK; t += 512) {
        int sg = seg_of(t, pos);
        float sw = (sg < STK) ? sa[t] / segsum[sg] * sattn[sg] : 0.f;
        o_cov[b * TK + t] = cov[b * TK + t] + sw;
    }
}

// ---------------------------------------------------------------------------
// c_t[b,n] = sum_t attn[b,t] * enc_out[b,t,n]
// grid (B, TSPLIT); each block handles TK/TSPLIT tokens, float4 per thread,
// atomicAdd partials into zeroed c_t.  Streams encoder_outputs.
// ---------------------------------------------------------------------------
#define TSPLIT 32
#define TCHUNK (TK / TSPLIT)   // 64

__global__ void ctx_kernel(const float* __restrict__ enc,
                           const float* __restrict__ attn,
                           float* __restrict__ o_ct)
{
    __shared__ float sh_a[TCHUNK];
    int b = blockIdx.x, sp = blockIdx.y;
    int tid = threadIdx.x;   // 128 threads, each owns a float4 (N/4 == 128)
    int t0 = sp * TCHUNK;
    if (tid < TCHUNK) sh_a[tid] = attn[b * TK + t0 + tid];
    __syncthreads();
    const float4* ev = (const float4*)enc;
    size_t base = ((size_t)b * TK + t0) * (N / 4) + tid;
    float4 acc = make_float4(0.f, 0.f, 0.f, 0.f);
#pragma unroll 8
    for (int i = 0; i < TCHUNK; i++) {
        float a = sh_a[i];
        float4 e = ev[base + (size_t)i * (N / 4)];
        acc.x = fmaf(a, e.x, acc.x);
        acc.y = fmaf(a, e.y, acc.y);
        acc.z = fmaf(a, e.z, acc.z);
        acc.w = fmaf(a, e.w, acc.w);
    }
    float* o = o_ct + (size_t)b * N + tid * 4;
    atomicAdd(o + 0, acc.x);
    atomicAdd(o + 1, acc.y);
    atomicAdd(o + 2, acc.z);
    atomicAdd(o + 3, acc.w);
}

// ---------------------------------------------------------------------------
extern "C" void kernel_launch(void* const* d_in, const int* in_sizes, int n_in,
                              void* d_out, int out_size)
{
    const float* s_t_hat  = (const float*)d_in[0];
    const int*   spos     = (const int*)  d_in[1];
    const float* enc_out  = (const float*)d_in[2];
    const float* enc_feat = (const float*)d_in[3];
    const float* mask     = (const float*)d_in[4];
    const float* s_sent   = (const float*)d_in[5];
    const float* sout     = (const float*)d_in[6];
    const float* sfeat    = (const float*)d_in[7];
    const float* smask    = (const float*)d_in[8];
    const float* cov      = (const float*)d_in[9];
    const float* Wd       = (const float*)d_in[10];
    const float* bd       = (const float*)d_in[11];
    const float* vw       = (const float*)d_in[12];
    const float* Wsd      = (const float*)d_in[13];
    const float* bsd      = (const float*)d_in[14];
    const float* svw      = (const float*)d_in[15];
    const float* wc       = (const float*)d_in[16];

    float* out     = (float*)d_out;
    float* o_ct    = out + OFF_CT;
    float* o_attn  = out + OFF_ATTN;
    float* o_cov   = out + OFF_COV;
    float* o_sct   = out + OFF_SCT;
    float* o_sattn = out + OFF_SATTN;

    // dec GEMVs (word + sentence): B*N warps each
    dec_kernel<<<(B * N) / 8, 256>>>(s_t_hat, Wd, bd, 0);
    dec_kernel<<<(B * N) / 8, 256>>>(s_sent, Wsd, bsd, 1);

    // scores: warp per token
    score_kernel<<<(B * TK) / 8, 256>>>(enc_feat, vw, wc, cov, TK, 0);
    score_kernel<<<(B * STK) / 8, 256>>>(sfeat, svw, nullptr, nullptr, STK, 1);

    // sentence softmax + sentence context
    sent_kernel<<<B, 256>>>(smask, sout, o_sattn, o_sct);

    // word softmax + segment renorm + coverage (+ zero c_t)
    word_softmax_kernel<<<B, 512>>>(mask, cov, spos, o_sattn, o_attn, o_cov, o_ct);

    // word context reduction
    ctx_kernel<<<dim3(B, TSPLIT), 128>>>(enc_out, o_attn, o_ct);
}